// round 6
// baseline (speedup 1.0000x reference)
#include <cuda_runtime.h>
#include <cstdint>

#define N_   16
#define T_   32
#define D_   768
#define L_   196
#define DC   4
#define NCH  (D_ / DC)   // 192 chunks
#define NLB  7
#define NBUF 3

typedef unsigned long long u64;

// softmaxed attention weights, attn[((n*T + t)*T + s)*L + l]  (12.8 MB)
__device__ float g_attn[N_ * T_ * T_ * L_];

extern __shared__ float smem_[];

// ---- float-index layout helpers ----
// scores kernel: k [NBUF][DC][32][32] | q [NBUF][DC][16][32] | pe [NBUF][32][4]
#define A_SK(b, dd, s, l)  ((b) * 4096 + (dd) * 1024 + (s) * 32 + (l))
#define A_SQ(b, dd, t, l)  (12288 + (b) * 2048 + (dd) * 512 + (t) * 32 + (l))
#define A_SPE(b, l, dd)    (18432 + (b) * 128 + (l) * 4 + (dd))
#define A_SMEM_BYTES       ((18432 + NBUF * 128) * 4)      // 75264 B

// out kernel: k [NBUF][DC][32][32] | pe [NBUF][32][4]
#define B_SK(b, dd, s, l)  ((b) * 4096 + (dd) * 1024 + (s) * 32 + (l))
#define B_SPE(b, l, dd)    (12288 + (b) * 128 + (l) * 4 + (dd))
#define B_SMEM_BYTES       ((12288 + NBUF * 128) * 4)      // 50688 B

// ---- packed f32x2 helpers ----
__device__ __forceinline__ u64 pack2(float x, float y) {
    u64 r; asm("mov.b64 %0, {%1, %2};" : "=l"(r) : "f"(x), "f"(y)); return r;
}
__device__ __forceinline__ void unpack2(u64 v, float& x, float& y) {
    asm("mov.b64 {%0, %1}, %2;" : "=f"(x), "=f"(y) : "l"(v));
}
__device__ __forceinline__ u64 fma2_(u64 a, u64 b, u64 c) {
    u64 r; asm("fma.rn.f32x2 %0, %1, %2, %3;" : "=l"(r) : "l"(a), "l"(b), "l"(c)); return r;
}
__device__ __forceinline__ u64 add2_(u64 a, u64 b) {
    u64 r; asm("add.rn.f32x2 %0, %1, %2;" : "=l"(r) : "l"(a), "l"(b)); return r;
}

// ---- cp.async ----
__device__ __forceinline__ void cp16(uint32_t dst, const float* src) {
    asm volatile("cp.async.ca.shared.global [%0], [%1], 16;" :: "r"(dst), "l"(src));
}
__device__ __forceinline__ void cp_commit() { asm volatile("cp.async.commit_group;"); }
__device__ __forceinline__ void cp_wait1()  { asm volatile("cp.async.wait_group 1;"); }
__device__ __forceinline__ void cp_wait0()  { asm volatile("cp.async.wait_group 0;"); }

// =====================================================================
// Kernel A: scores + softmax.  S'[t,s,l] = sum_d (q+eq)[t,d,l]*k[s,d,l]
// Grid (7, 16, 2), block 128 = 32 l-lanes x 4 warps (4 t each).
// q, k, peq all cp.async-staged; 1 barrier per DC=4 chunk; NBUF=3.
// __launch_bounds__(128,3): 12 warps/SM.
// =====================================================================
__global__ __launch_bounds__(128, 3)
void scores_kernel(const float* __restrict__ q, const float* __restrict__ k,
                   const float* __restrict__ peq)
{
    const int tid  = threadIdx.x;
    const int lane = tid & 31;
    const int tg   = tid >> 5;
    const int l0   = blockIdx.x * 32;
    const int n    = blockIdx.y;
    const int tz0  = blockIdx.z * 16;        // CTA's first t
    const int t0   = tz0 + tg * 4;           // warp's first t
    const int l    = l0 + lane;
    const bool lv  = (l < L_);

    // zero smem once; invalid-l slots stay zero
    for (int i = tid; i < (A_SMEM_BYTES / 4); i += 128) smem_[i] = 0.f;
    __syncthreads();

    const uint32_t sbase = (uint32_t)__cvta_generic_to_shared(smem_);

    // staging maps (fixed per thread). GUARDS ARE QUAD-BASED (l0+quad<L_),
    // NOT lane-based — this was the round-5 correctness bug.
    const int ll  = (tid & 7) * 4;            // k: l-quad
    const int rr  = tid >> 3;                 // 0..15
    const bool kv_ok = (l0 + ll < L_);
    const int lq  = (tid & 7) * 4;            // q: l-quad
    const int qt  = tid >> 3;                 // q: t-local 0..15
    const bool qv_ok = (l0 + lq < L_);
    const bool pe_ok = (tid < 32) && (l0 + tid < L_);

    const float* kb0 = k + (size_t)n * T_ * D_ * L_ + l0 + ll;
    const float* qb0 = q + ((size_t)n * T_ + tz0) * D_ * L_ + l0 + lq;
    const float* pb0 = peq + (size_t)(l0 + (tid & 31)) * D_;

    auto issue = [&](int c, int buf) {
        const size_t d0L = (size_t)(c * DC) * L_;
        if (kv_ok) {
#pragma unroll
            for (int i = 0; i < 8; i++) {
                int r  = i * 16 + rr;          // 0..127
                int s  = r & 31;
                int dd = r >> 5;               // 0..3
                cp16(sbase + A_SK(buf, dd, s, ll) * 4,
                     kb0 + ((size_t)s * D_ + dd) * L_ + d0L);
            }
        }
        if (qv_ok) {
#pragma unroll
            for (int dd = 0; dd < 4; dd++) {
                cp16(sbase + A_SQ(buf, dd, qt, lq) * 4,
                     qb0 + ((size_t)qt * D_ + dd) * L_ + d0L);
            }
        }
        if (pe_ok)
            cp16(sbase + A_SPE(buf, tid, 0) * 4, pb0 + c * DC);
        cp_commit();
    };

    u64 acc[4][16];
#pragma unroll
    for (int i = 0; i < 4; i++)
#pragma unroll
        for (int sp = 0; sp < 16; sp++) acc[i][sp] = 0ULL;

    issue(0, 0);
    issue(1, 1);

    for (int c = 0; c < NCH; ++c) {
        if (c + 1 < NCH) cp_wait1(); else cp_wait0();
        __syncthreads();
        if (c + 2 < NCH) issue(c + 2, (c + 2) % NBUF);

        const int buf = c % NBUF;
        const int tb  = tg * 4;
#pragma unroll
        for (int dd = 0; dd < DC; dd++) {
            float eq = smem_[A_SPE(buf, lane, dd)];
            u64 qv[4];
#pragma unroll
            for (int i = 0; i < 4; i++) {
                float qs = smem_[A_SQ(buf, dd, tb + i, lane)] + eq;
                qv[i] = pack2(qs, qs);
            }
            const float* kb = &smem_[A_SK(buf, dd, 0, lane)];
#pragma unroll
            for (int sp = 0; sp < 16; sp++) {
                u64 kv = pack2(kb[(2 * sp) * 32], kb[(2 * sp + 1) * 32]);
                acc[0][sp] = fma2_(qv[0], kv, acc[0][sp]);
                acc[1][sp] = fma2_(qv[1], kv, acc[1][sp]);
                acc[2][sp] = fma2_(qv[2], kv, acc[2][sp]);
                acc[3][sp] = fma2_(qv[3], kv, acc[3][sp]);
            }
        }
    }

    // softmax over s (thread-local), write attention weights
    if (lv) {
        const float scale = 0.03608439182435161f;  // 1/sqrt(768)
#pragma unroll
        for (int i = 0; i < 4; i++) {
            float v[32];
#pragma unroll
            for (int sp = 0; sp < 16; sp++) unpack2(acc[i][sp], v[2 * sp], v[2 * sp + 1]);
            float m = -1e30f;
#pragma unroll
            for (int s = 0; s < 32; s++) { v[s] *= scale; m = fmaxf(m, v[s]); }
            float sum = 0.f;
#pragma unroll
            for (int s = 0; s < 32; s++) { float e = __expf(v[s] - m); v[s] = e; sum += e; }
            float inv = 1.f / sum;
            float* ap = &g_attn[(((size_t)n * T_ + t0 + i) * T_) * L_ + l];
#pragma unroll
            for (int s = 0; s < 32; s++) ap[s * L_] = v[s] * inv;
        }
    }
}

// =====================================================================
// Kernel B: out[n,t,l,d] = sum_s attn[n,t,s,l]*k[n,s,d,l] + pek[l,d]
// Grid (7, 16, 2), block 128, __launch_bounds__(128,3).
// attn rows (4t x 32s) register-resident; k + pek cp.async-staged.
// =====================================================================
__global__ __launch_bounds__(128, 3)
void out_kernel(const float* __restrict__ k, const float* __restrict__ pek,
                float* __restrict__ out)
{
    const int tid  = threadIdx.x;
    const int lane = tid & 31;
    const int tg   = tid >> 5;
    const int l0   = blockIdx.x * 32;
    const int n    = blockIdx.y;
    const int t0   = blockIdx.z * 16 + tg * 4;
    const int l    = l0 + lane;
    const bool lv  = (l < L_);

    for (int i = tid; i < (B_SMEM_BYTES / 4); i += 128) smem_[i] = 0.f;

    const uint32_t sbase = (uint32_t)__cvta_generic_to_shared(smem_);

    const int ll  = (tid & 7) * 4;
    const int rr  = tid >> 3;
    const bool kv_ok = (l0 + ll < L_);
    const bool pe_ok = (tid < 32) && (l0 + tid < L_);

    const float* kb0 = k + (size_t)n * T_ * D_ * L_ + l0 + ll;
    const float* pb0 = pek + (size_t)(l0 + (tid & 31)) * D_;

    // attention rows for my 4 t's (coalesced along l)
    float ar[4][32];
#pragma unroll
    for (int i = 0; i < 4; i++)
#pragma unroll
        for (int s = 0; s < 32; s++)
            ar[i][s] = lv ? g_attn[(((size_t)n * T_ + t0 + i) * T_ + s) * L_ + l] : 0.f;

    __syncthreads();

    auto issue = [&](int c, int buf) {
        const size_t d0L = (size_t)(c * DC) * L_;
        if (kv_ok) {
#pragma unroll
            for (int i = 0; i < 8; i++) {
                int r  = i * 16 + rr;
                int s  = r & 31;
                int dd = r >> 5;
                cp16(sbase + B_SK(buf, dd, s, ll) * 4,
                     kb0 + ((size_t)s * D_ + dd) * L_ + d0L);
            }
        }
        if (pe_ok)
            cp16(sbase + B_SPE(buf, tid, 0) * 4, pb0 + c * DC);
        cp_commit();
    };

    issue(0, 0);
    issue(1, 1);

    for (int c = 0; c < NCH; ++c) {
        if (c + 1 < NCH) cp_wait1(); else cp_wait0();
        __syncthreads();
        if (c + 2 < NCH) issue(c + 2, (c + 2) % NBUF);

        const int buf = c % NBUF;

        u64 oc[4][2];
#pragma unroll
        for (int i = 0; i < 4; i++) { oc[i][0] = 0ULL; oc[i][1] = 0ULL; }

        const float* kb = &smem_[B_SK(buf, 0, 0, lane)];
#pragma unroll
        for (int s = 0; s < 32; s++) {
            u64 kv0 = pack2(kb[s * 32], kb[1024 + s * 32]);
            u64 kv1 = pack2(kb[2048 + s * 32], kb[3072 + s * 32]);
#pragma unroll
            for (int i = 0; i < 4; i++) {
                u64 a2 = pack2(ar[i][s], ar[i][s]);
                oc[i][0] = fma2_(a2, kv0, oc[i][0]);
                oc[i][1] = fma2_(a2, kv1, oc[i][1]);
            }
        }

        if (lv) {
            const u64* pep = reinterpret_cast<const u64*>(&smem_[B_SPE(buf, lane, 0)]);
            u64 pe0 = pep[0];
            u64 pe1 = pep[1];
            const int d0 = c * DC;
#pragma unroll
            for (int i = 0; i < 4; i++) {
                u64 r0 = add2_(oc[i][0], pe0);
                u64 r1 = add2_(oc[i][1], pe1);
                float4 f;
                unpack2(r0, f.x, f.y);
                unpack2(r1, f.z, f.w);
                *reinterpret_cast<float4*>(
                    out + (((size_t)n * T_ + t0 + i) * L_ + l) * D_ + d0) = f;
            }
        }
    }
}

extern "C" void kernel_launch(void* const* d_in, const int* in_sizes, int n_in,
                              void* d_out, int out_size)
{
    const float* q   = (const float*)d_in[0];
    const float* k   = (const float*)d_in[1];
    const float* peq = (const float*)d_in[2];
    const float* pek = (const float*)d_in[3];
    float* out = (float*)d_out;

    static int configured = 0;
    if (!configured) {
        cudaFuncSetAttribute(scores_kernel,
                             cudaFuncAttributeMaxDynamicSharedMemorySize, A_SMEM_BYTES);
        cudaFuncSetAttribute(out_kernel,
                             cudaFuncAttributeMaxDynamicSharedMemorySize, B_SMEM_BYTES);
        configured = 1;
    }

    dim3 grid(NLB, N_, 2);
    scores_kernel<<<grid, 128, A_SMEM_BYTES>>>(q, k, peq);
    out_kernel<<<grid, 128, B_SMEM_BYTES>>>(k, pek, out);
}

// round 7
// speedup vs baseline: 1.1002x; 1.1002x over previous
#include <cuda_runtime.h>
#include <cstdint>

#define N_   16
#define T_   32
#define D_   768
#define L_   196
#define NLB  7

// scores kernel chunking
#define SDC  8
#define SNB  3
#define SNCH (D_ / SDC)     // 96
// out kernel chunking
#define ODC  4
#define ONB  4
#define ONCH (D_ / ODC)     // 192

typedef unsigned long long u64;

// softmaxed attention weights, attn[((n*T + t)*T + s)*L + l]  (12.8 MB)
__device__ float g_attn[N_ * T_ * T_ * L_];

extern __shared__ float smem_[];

// k ring layouts (floats)
#define A_SK(b, dd, s, l)  ((((b) * SDC + (dd)) * 32 + (s)) * 32 + (l))
#define A_SMEM_BYTES       (SNB * SDC * 32 * 32 * 4)   // 98304
#define B_SK(b, dd, s, l)  ((((b) * ODC + (dd)) * 32 + (s)) * 32 + (l))
#define B_SMEM_BYTES       (ONB * ODC * 32 * 32 * 4)   // 65536

// ---- packed f32x2 helpers ----
__device__ __forceinline__ u64 pack2(float x, float y) {
    u64 r; asm("mov.b64 %0, {%1, %2};" : "=l"(r) : "f"(x), "f"(y)); return r;
}
__device__ __forceinline__ void unpack2(u64 v, float& x, float& y) {
    asm("mov.b64 {%0, %1}, %2;" : "=f"(x), "=f"(y) : "l"(v));
}
__device__ __forceinline__ u64 fma2_(u64 a, u64 b, u64 c) {
    u64 r; asm("fma.rn.f32x2 %0, %1, %2, %3;" : "=l"(r) : "l"(a), "l"(b), "l"(c)); return r;
}

// ---- cp.async ----
__device__ __forceinline__ void cp16(uint32_t dst, const float* src) {
    asm volatile("cp.async.ca.shared.global [%0], [%1], 16;" :: "r"(dst), "l"(src));
}
__device__ __forceinline__ void cp_commit() { asm volatile("cp.async.commit_group;"); }
__device__ __forceinline__ void cp_wait2()  { asm volatile("cp.async.wait_group 2;"); }
__device__ __forceinline__ void cp_wait1()  { asm volatile("cp.async.wait_group 1;"); }
__device__ __forceinline__ void cp_wait0()  { asm volatile("cp.async.wait_group 0;"); }

// =====================================================================
// Kernel A: scores + softmax.  S'[t,s,l] = sum_d (q+eq)[t,d,l]*k[s,d,l]
// Grid (7,16,2), block 256 = 32 l-lanes x 8 warps, each warp 2 t's.
// k cp.async ring (DC=8, NBUF=3, 1 barrier/chunk); q register-prefetched
// with peq folded in at load (the (q+eq)·ek term cancels in softmax).
// =====================================================================
__global__ __launch_bounds__(256, 2)
void scores_kernel(const float* __restrict__ q, const float* __restrict__ k,
                   const float* __restrict__ peq)
{
    const int tid  = threadIdx.x;
    const int lane = tid & 31;
    const int tg   = tid >> 5;               // 0..7
    const int l0   = blockIdx.x * 32;
    const int n    = blockIdx.y;
    const int t0   = blockIdx.z * 16 + tg * 2;
    const int l    = l0 + lane;
    const bool lv  = (l < L_);

    // zero smem once; guarded-off l-quads stay zero forever
    for (int i = tid; i < (A_SMEM_BYTES / 4); i += 256) smem_[i] = 0.f;
    __syncthreads();

    const uint32_t sbase = (uint32_t)__cvta_generic_to_shared(smem_);

    // k staging map: 2048 quads/chunk, 8 per thread
    const int c4  = tid & 7;
    const int ll  = c4 * 4;
    const bool kv_ok = (l0 + ll < L_);       // quad-based guard (L%4==0)
    const int srow = (tid >> 3) & 31;        // s for i=0; +0 each i (dd varies)
    (void)srow;
    const float* kb0 = k + (size_t)n * T_ * D_ * L_ + l0 + ll;

    auto issue = [&](int c, int buf) {
        const size_t d0L = (size_t)(c * SDC) * L_;
        if (kv_ok) {
#pragma unroll
            for (int i = 0; i < 8; i++) {
                int idx = i * 256 + tid;      // 0..2047
                int s   = (idx >> 3) & 31;
                int dd  = idx >> 8;           // 0..7
                cp16(sbase + A_SK(buf, dd, s, ll) * 4,
                     kb0 + ((size_t)s * D_ + dd) * L_ + d0L);
            }
        }
        cp_commit();
    };

    // q chunk with peq folded in
    auto loadq = [&](int c, float (&qr)[2][SDC]) {
        const int d0 = c * SDC;
        if (lv) {
            float e[8];
            float4 e0 = *reinterpret_cast<const float4*>(peq + (size_t)l * D_ + d0);
            float4 e1 = *reinterpret_cast<const float4*>(peq + (size_t)l * D_ + d0 + 4);
            e[0] = e0.x; e[1] = e0.y; e[2] = e0.z; e[3] = e0.w;
            e[4] = e1.x; e[5] = e1.y; e[6] = e1.z; e[7] = e1.w;
#pragma unroll
            for (int i = 0; i < 2; i++)
#pragma unroll
                for (int dd = 0; dd < SDC; dd++)
                    qr[i][dd] = __ldg(q + (((size_t)n * T_ + t0 + i) * D_ + d0 + dd) * L_ + l)
                                + e[dd];
        } else {
#pragma unroll
            for (int i = 0; i < 2; i++)
#pragma unroll
                for (int dd = 0; dd < SDC; dd++) qr[i][dd] = 0.f;
        }
    };

    u64 acc[2][16];
#pragma unroll
    for (int i = 0; i < 2; i++)
#pragma unroll
        for (int sp = 0; sp < 16; sp++) acc[i][sp] = 0ULL;

    float qc[2][SDC], qn[2][SDC];
    issue(0, 0);
    issue(1, 1);
    loadq(0, qc);

    for (int c = 0; c < SNCH; ++c) {
        if (c + 1 < SNCH) cp_wait1(); else cp_wait0();
        __syncthreads();
        if (c + 2 < SNCH) issue(c + 2, (c + 2) % SNB);
        if (c + 1 < SNCH) loadq(c + 1, qn);

        const int buf = c % SNB;
#pragma unroll
        for (int dd = 0; dd < SDC; dd++) {
            u64 qv0 = pack2(qc[0][dd], qc[0][dd]);
            u64 qv1 = pack2(qc[1][dd], qc[1][dd]);
            const float* kb = &smem_[A_SK(buf, dd, 0, lane)];
#pragma unroll
            for (int sp = 0; sp < 16; sp++) {
                u64 kv = pack2(kb[(2 * sp) * 32], kb[(2 * sp + 1) * 32]);
                acc[0][sp] = fma2_(qv0, kv, acc[0][sp]);
                acc[1][sp] = fma2_(qv1, kv, acc[1][sp]);
            }
        }
#pragma unroll
        for (int i = 0; i < 2; i++)
#pragma unroll
            for (int dd = 0; dd < SDC; dd++) qc[i][dd] = qn[i][dd];
    }

    // softmax over s (thread-local), write attention weights
    if (lv) {
        const float scale = 0.03608439182435161f;  // 1/sqrt(768)
#pragma unroll
        for (int i = 0; i < 2; i++) {
            float v[32];
#pragma unroll
            for (int sp = 0; sp < 16; sp++) unpack2(acc[i][sp], v[2 * sp], v[2 * sp + 1]);
            float m = -1e30f;
#pragma unroll
            for (int s = 0; s < 32; s++) { v[s] *= scale; m = fmaxf(m, v[s]); }
            float sum = 0.f;
#pragma unroll
            for (int s = 0; s < 32; s++) { float e = __expf(v[s] - m); v[s] = e; sum += e; }
            float inv = 1.f / sum;
            float* ap = &g_attn[(((size_t)n * T_ + t0 + i) * T_) * L_ + l];
#pragma unroll
            for (int s = 0; s < 32; s++) ap[s * L_] = v[s] * inv;
        }
    }
}

// =====================================================================
// Kernel B: out[n,t,l,d] = sum_s attn[n,t,s,l]*k[n,s,d,l] + pek[l,d]
// Grid (7,16,2), block 256, each warp 2 t's. attn rows register-resident.
// k cp.async ring DC=4, NBUF=4, 2-chunk lookahead. pek register-prefetched.
// =====================================================================
__global__ __launch_bounds__(256, 2)
void out_kernel(const float* __restrict__ k, const float* __restrict__ pek,
                float* __restrict__ out)
{
    const int tid  = threadIdx.x;
    const int lane = tid & 31;
    const int tg   = tid >> 5;
    const int l0   = blockIdx.x * 32;
    const int n    = blockIdx.y;
    const int t0   = blockIdx.z * 16 + tg * 2;
    const int l    = l0 + lane;
    const bool lv  = (l < L_);

    for (int i = tid; i < (B_SMEM_BYTES / 4); i += 256) smem_[i] = 0.f;

    const uint32_t sbase = (uint32_t)__cvta_generic_to_shared(smem_);

    const int c4  = tid & 7;
    const int ll  = c4 * 4;
    const bool kv_ok = (l0 + ll < L_);
    const float* kb0 = k + (size_t)n * T_ * D_ * L_ + l0 + ll;

    // attention rows for my 2 t's (coalesced along l)
    float ar[2][32];
#pragma unroll
    for (int i = 0; i < 2; i++)
#pragma unroll
        for (int s = 0; s < 32; s++)
            ar[i][s] = lv ? g_attn[(((size_t)n * T_ + t0 + i) * T_ + s) * L_ + l] : 0.f;

    __syncthreads();

    auto issue = [&](int c, int buf) {
        const size_t d0L = (size_t)(c * ODC) * L_;
        if (kv_ok) {
#pragma unroll
            for (int i = 0; i < 4; i++) {
                int idx = i * 256 + tid;      // 0..1023
                int s   = (idx >> 3) & 31;
                int dd  = idx >> 8;           // 0..3
                cp16(sbase + B_SK(buf, dd, s, ll) * 4,
                     kb0 + ((size_t)s * D_ + dd) * L_ + d0L);
            }
        }
        cp_commit();
    };

    auto loadpe = [&](int c, float4& pe) {
        pe = lv ? *reinterpret_cast<const float4*>(pek + (size_t)l * D_ + c * ODC)
                : make_float4(0.f, 0.f, 0.f, 0.f);
    };

    issue(0, 0);
    issue(1, 1);
    issue(2, 2);

    float4 pec, pen;
    loadpe(0, pec);

    for (int c = 0; c < ONCH; ++c) {
        if (c + 2 < ONCH) cp_wait2();
        else if (c + 1 < ONCH) cp_wait1();
        else cp_wait0();
        __syncthreads();
        if (c + 3 < ONCH) issue(c + 3, (c + 3) % ONB);
        if (c + 1 < ONCH) loadpe(c + 1, pen);

        const int buf = c % ONB;

        u64 oc[2][2];
        oc[0][0] = oc[0][1] = oc[1][0] = oc[1][1] = 0ULL;

        const float* kb = &smem_[B_SK(buf, 0, 0, lane)];
#pragma unroll
        for (int s = 0; s < 32; s++) {
            u64 kv0 = pack2(kb[s * 32],        kb[1024 + s * 32]);
            u64 kv1 = pack2(kb[2048 + s * 32], kb[3072 + s * 32]);
            u64 a20 = pack2(ar[0][s], ar[0][s]);
            u64 a21 = pack2(ar[1][s], ar[1][s]);
            oc[0][0] = fma2_(a20, kv0, oc[0][0]);
            oc[0][1] = fma2_(a20, kv1, oc[0][1]);
            oc[1][0] = fma2_(a21, kv0, oc[1][0]);
            oc[1][1] = fma2_(a21, kv1, oc[1][1]);
        }

        if (lv) {
            const int d0 = c * ODC;
#pragma unroll
            for (int i = 0; i < 2; i++) {
                float4 f;
                unpack2(oc[i][0], f.x, f.y);
                unpack2(oc[i][1], f.z, f.w);
                f.x += pec.x; f.y += pec.y; f.z += pec.z; f.w += pec.w;
                *reinterpret_cast<float4*>(
                    out + (((size_t)n * T_ + t0 + i) * L_ + l) * D_ + d0) = f;
            }
        }
        pec = pen;
    }
}

extern "C" void kernel_launch(void* const* d_in, const int* in_sizes, int n_in,
                              void* d_out, int out_size)
{
    const float* q   = (const float*)d_in[0];
    const float* k   = (const float*)d_in[1];
    const float* peq = (const float*)d_in[2];
    const float* pek = (const float*)d_in[3];
    float* out = (float*)d_out;

    static int configured = 0;
    if (!configured) {
        cudaFuncSetAttribute(scores_kernel,
                             cudaFuncAttributeMaxDynamicSharedMemorySize, A_SMEM_BYTES);
        cudaFuncSetAttribute(out_kernel,
                             cudaFuncAttributeMaxDynamicSharedMemorySize, B_SMEM_BYTES);
        configured = 1;
    }

    dim3 grid(NLB, N_, 2);
    scores_kernel<<<grid, 256, A_SMEM_BYTES>>>(q, k, peq);
    out_kernel<<<grid, 256, B_SMEM_BYTES>>>(k, pek, out);
}

// round 9
// speedup vs baseline: 1.5807x; 1.4368x over previous
#include <cuda_runtime.h>
#include <cstdint>

#define N_   16
#define T_   32
#define D_   768
#define DH   (D_ / 2)       // 384 per d-half
#define L_   196
#define NLB  7
#define DC   4
#define NCH  (DH / DC)      // 96 chunks per d-half
#define NBUF 3              // MUST exceed lookahead (=2)

typedef unsigned long long u64;

// raw partial scores per d-half: g_part[dz][((n*T+t)*T+s)*L+l]  (2 x 12.8 MB)
__device__ float g_part[2][N_ * T_ * T_ * L_];

// ---- packed f32x2 helpers ----
__device__ __forceinline__ u64 pack2(float x, float y) {
    u64 r; asm("mov.b64 %0, {%1, %2};" : "=l"(r) : "f"(x), "f"(y)); return r;
}
__device__ __forceinline__ void unpack2(u64 v, float& x, float& y) {
    asm("mov.b64 {%0, %1}, %2;" : "=f"(x), "=f"(y) : "l"(v));
}
__device__ __forceinline__ u64 fma2_(u64 a, u64 b, u64 c) {
    u64 r; asm("fma.rn.f32x2 %0, %1, %2, %3;" : "=l"(r) : "l"(a), "l"(b), "l"(c)); return r;
}

// ---- cp.async ----
__device__ __forceinline__ void cp16(uint32_t dst, const float* src) {
    asm volatile("cp.async.ca.shared.global [%0], [%1], 16;" :: "r"(dst), "l"(src));
}
__device__ __forceinline__ void cp_commit() { asm volatile("cp.async.commit_group;"); }
__device__ __forceinline__ void cp_wait1()  { asm volatile("cp.async.wait_group 1;"); }
__device__ __forceinline__ void cp_wait0()  { asm volatile("cp.async.wait_group 0;"); }

// k ring: [NBUF][DC][32 s][32 l]  (48 KB static -> 3 CTAs/SM = 144 KB)
#define SK(b, dd, s, l) ((((b) * DC + (dd)) * 32 + (s)) * 32 + (l))

// =====================================================================
// Kernel A: partial scores over one d-half.
// Grid (7, 16, 4): z = tz + 2*dz. Block 128 = 32 l-lanes x 4 warps,
// each warp 4 t's. q register-prefetched with peq folded in (the
// (q+eq)·ek term is constant over s and cancels in the softmax).
// Writes RAW partial scores to g_part[dz].
// =====================================================================
__global__ __launch_bounds__(128, 3)
void scores_kernel(const float* __restrict__ q, const float* __restrict__ k,
                   const float* __restrict__ peq)
{
    __shared__ float sk[NBUF * DC * 32 * 32];

    const int tid  = threadIdx.x;
    const int lane = tid & 31;
    const int tg   = tid >> 5;               // 0..3
    const int l0   = blockIdx.x * 32;
    const int n    = blockIdx.y;
    const int tz   = blockIdx.z & 1;
    const int dz   = blockIdx.z >> 1;
    const int t0   = tz * 16 + tg * 4;
    const int l    = l0 + lane;
    const bool lv  = (l < L_);
    const int dbase = dz * DH;

    // zero smem once; guarded-off l-quads stay zero
    for (int i = tid; i < NBUF * DC * 32 * 32; i += 128) sk[i] = 0.f;
    __syncthreads();

    const uint32_t sbase = (uint32_t)__cvta_generic_to_shared(sk);

    // staging map: 1024 quads/chunk, 8 per thread; quad-based guard
    const int ll  = (tid & 7) * 4;
    const bool kv_ok = (l0 + ll < L_);
    const float* kb0 = k + ((size_t)n * T_ * D_ + dbase) * L_ + l0 + ll;

    auto issue = [&](int c, int buf) {
        const size_t cL = (size_t)(c * DC) * L_;
        if (kv_ok) {
#pragma unroll
            for (int i = 0; i < 8; i++) {
                int r  = i * 16 + (tid >> 3);  // 0..127
                int s  = r & 31;
                int dd = r >> 5;               // 0..3
                cp16(sbase + (uint32_t)SK(buf, dd, s, ll) * 4,
                     kb0 + ((size_t)s * D_ + dd) * L_ + cL);
            }
        }
        cp_commit();
    };

    const float* qb0 = q + ((size_t)n * T_ * D_ + dbase) * L_ + l;
    const float* pb0 = peq + (size_t)l * D_ + dbase;

    auto loadq = [&](int c, float (&qr)[4][DC]) {
        if (lv) {
            float4 e = *reinterpret_cast<const float4*>(pb0 + c * DC);
            const size_t cL = (size_t)(c * DC) * L_;
#pragma unroll
            for (int i = 0; i < 4; i++) {
                qr[i][0] = __ldg(qb0 + ((size_t)(t0 + i) * D_ + 0) * L_ + cL) + e.x;
                qr[i][1] = __ldg(qb0 + ((size_t)(t0 + i) * D_ + 1) * L_ + cL) + e.y;
                qr[i][2] = __ldg(qb0 + ((size_t)(t0 + i) * D_ + 2) * L_ + cL) + e.z;
                qr[i][3] = __ldg(qb0 + ((size_t)(t0 + i) * D_ + 3) * L_ + cL) + e.w;
            }
        } else {
#pragma unroll
            for (int i = 0; i < 4; i++)
#pragma unroll
                for (int dd = 0; dd < DC; dd++) qr[i][dd] = 0.f;
        }
    };

    u64 acc[4][16];
#pragma unroll
    for (int i = 0; i < 4; i++)
#pragma unroll
        for (int sp = 0; sp < 16; sp++) acc[i][sp] = 0ULL;

    float qc[4][DC], qn[4][DC];
    issue(0, 0);
    issue(1, 1);
    loadq(0, qc);

    for (int c = 0; c < NCH; ++c) {
        if (c + 1 < NCH) cp_wait1(); else cp_wait0();
        __syncthreads();
        if (c + 2 < NCH) issue(c + 2, (c + 2) % NBUF);   // (c+2)%3 != c%3, (c+1)%3
        if (c + 1 < NCH) loadq(c + 1, qn);

        const int buf = c % NBUF;
#pragma unroll
        for (int dd = 0; dd < DC; dd++) {
            u64 qv0 = pack2(qc[0][dd], qc[0][dd]);
            u64 qv1 = pack2(qc[1][dd], qc[1][dd]);
            u64 qv2 = pack2(qc[2][dd], qc[2][dd]);
            u64 qv3 = pack2(qc[3][dd], qc[3][dd]);
            const float* kb = &sk[SK(buf, dd, 0, lane)];
#pragma unroll
            for (int sp = 0; sp < 16; sp++) {
                u64 kv = pack2(kb[(2 * sp) * 32], kb[(2 * sp + 1) * 32]);
                acc[0][sp] = fma2_(qv0, kv, acc[0][sp]);
                acc[1][sp] = fma2_(qv1, kv, acc[1][sp]);
                acc[2][sp] = fma2_(qv2, kv, acc[2][sp]);
                acc[3][sp] = fma2_(qv3, kv, acc[3][sp]);
            }
        }
#pragma unroll
        for (int i = 0; i < 4; i++)
#pragma unroll
            for (int dd = 0; dd < DC; dd++) qc[i][dd] = qn[i][dd];
    }

    // write raw partial scores (coalesced along l)
    if (lv) {
#pragma unroll
        for (int i = 0; i < 4; i++) {
            float* ap = &g_part[dz][(((size_t)n * T_ + t0 + i) * T_) * L_ + l];
#pragma unroll
            for (int sp = 0; sp < 16; sp++) {
                float x, y;
                unpack2(acc[i][sp], x, y);
                ap[(2 * sp) * L_]     = x;
                ap[(2 * sp + 1) * L_] = y;
            }
        }
    }
}

// =====================================================================
// Kernel B: reduce partials + softmax (prologue, register-resident),
// then out[n,t,l,dhalf] = sum_s attn[t,s]*k[n,s,d,l] + pek[l,d].
// Grid (7, 16, 4): z = tz + 2*dz (dz = which d-half of the OUTPUT this
// CTA produces). Block 128, warp = 4 t's.
// =====================================================================
__global__ __launch_bounds__(128, 3)
void out_kernel(const float* __restrict__ k, const float* __restrict__ pek,
                float* __restrict__ out)
{
    __shared__ float sk[NBUF * DC * 32 * 32];

    const int tid  = threadIdx.x;
    const int lane = tid & 31;
    const int tg   = tid >> 5;
    const int l0   = blockIdx.x * 32;
    const int n    = blockIdx.y;
    const int tz   = blockIdx.z & 1;
    const int dz   = blockIdx.z >> 1;
    const int t0   = tz * 16 + tg * 4;
    const int l    = l0 + lane;
    const bool lv  = (l < L_);
    const int dbase = dz * DH;

    for (int i = tid; i < NBUF * DC * 32 * 32; i += 128) sk[i] = 0.f;
    __syncthreads();   // zero must be visible before any cp.async lands

    const uint32_t sbase = (uint32_t)__cvta_generic_to_shared(sk);

    const int ll  = (tid & 7) * 4;
    const bool kv_ok = (l0 + ll < L_);
    const float* kb0 = k + ((size_t)n * T_ * D_ + dbase) * L_ + l0 + ll;

    auto issue = [&](int c, int buf) {
        const size_t cL = (size_t)(c * DC) * L_;
        if (kv_ok) {
#pragma unroll
            for (int i = 0; i < 8; i++) {
                int r  = i * 16 + (tid >> 3);
                int s  = r & 31;
                int dd = r >> 5;
                cp16(sbase + (uint32_t)SK(buf, dd, s, ll) * 4,
                     kb0 + ((size_t)s * D_ + dd) * L_ + cL);
            }
        }
        cp_commit();
    };

    issue(0, 0);
    issue(1, 1);

    // ---- prologue: reduce partials + softmax into registers ----
    float ar[4][32];
    if (lv) {
        const float scale = 0.03608439182435161f;  // 1/sqrt(768)
#pragma unroll
        for (int i = 0; i < 4; i++) {
            const float* p0 = &g_part[0][(((size_t)n * T_ + t0 + i) * T_) * L_ + l];
            const float* p1 = &g_part[1][(((size_t)n * T_ + t0 + i) * T_) * L_ + l];
            float v[32];
            float m = -1e30f;
#pragma unroll
            for (int s = 0; s < 32; s++) {
                v[s] = (p0[s * L_] + p1[s * L_]) * scale;
                m = fmaxf(m, v[s]);
            }
            float sum = 0.f;
#pragma unroll
            for (int s = 0; s < 32; s++) { float e = __expf(v[s] - m); v[s] = e; sum += e; }
            float inv = 1.f / sum;
#pragma unroll
            for (int s = 0; s < 32; s++) ar[i][s] = v[s] * inv;
        }
    } else {
#pragma unroll
        for (int i = 0; i < 4; i++)
#pragma unroll
            for (int s = 0; s < 32; s++) ar[i][s] = 0.f;
    }

    const float* pb0 = pek + (size_t)l * D_ + dbase;

    for (int c = 0; c < NCH; ++c) {
        if (c + 1 < NCH) cp_wait1(); else cp_wait0();
        __syncthreads();
        if (c + 2 < NCH) issue(c + 2, (c + 2) % NBUF);

        const int buf = c % NBUF;

        u64 oc[4][2];
#pragma unroll
        for (int i = 0; i < 4; i++) { oc[i][0] = 0ULL; oc[i][1] = 0ULL; }

        const float* kb = &sk[SK(buf, 0, 0, lane)];
#pragma unroll
        for (int s = 0; s < 32; s++) {
            u64 kv0 = pack2(kb[s * 32],        kb[1024 + s * 32]);
            u64 kv1 = pack2(kb[2048 + s * 32], kb[3072 + s * 32]);
#pragma unroll
            for (int i = 0; i < 4; i++) {
                u64 a2 = pack2(ar[i][s], ar[i][s]);
                oc[i][0] = fma2_(a2, kv0, oc[i][0]);
                oc[i][1] = fma2_(a2, kv1, oc[i][1]);
            }
        }

        if (lv) {
            float4 pe = *reinterpret_cast<const float4*>(pb0 + c * DC);
            const int d0 = dbase + c * DC;
#pragma unroll
            for (int i = 0; i < 4; i++) {
                float4 f;
                unpack2(oc[i][0], f.x, f.y);
                unpack2(oc[i][1], f.z, f.w);
                f.x += pe.x; f.y += pe.y; f.z += pe.z; f.w += pe.w;
                *reinterpret_cast<float4*>(
                    out + (((size_t)n * T_ + t0 + i) * L_ + l) * D_ + d0) = f;
            }
        }
    }
}

extern "C" void kernel_launch(void* const* d_in, const int* in_sizes, int n_in,
                              void* d_out, int out_size)
{
    const float* q   = (const float*)d_in[0];
    const float* k   = (const float*)d_in[1];
    const float* peq = (const float*)d_in[2];
    const float* pek = (const float*)d_in[3];
    float* out = (float*)d_out;

    dim3 grid(NLB, N_, 4);
    scores_kernel<<<grid, 128>>>(q, k, peq);
    out_kernel<<<grid, 128>>>(k, pek, out);
}

// round 10
// speedup vs baseline: 1.6620x; 1.0514x over previous
#include <cuda_runtime.h>
#include <cstdint>

#define N_   16
#define T_   32
#define D_   768
#define DH   (D_ / 2)       // 384 per d-half
#define L_   196
#define NLB  7
#define DC   4
#define NCH  (DH / DC)      // 96 chunks per d-half (scores)
#define NBUF 3

typedef unsigned long long u64;

// raw partial scores per d-half (2 x 25.7 MB)
__device__ float g_part[2][N_ * T_ * T_ * L_];
// transposed k: kt[n][s][l][d]  (308 MB)
__device__ float g_kt[N_ * T_ * L_ * D_];
// softmaxed attn, duplicated f32x2: g_a2[n][s][t][l] (25.7 MB)
__device__ u64 g_a2[N_ * T_ * T_ * L_];

// ---- packed f32x2 helpers ----
__device__ __forceinline__ u64 pack2(float x, float y) {
    u64 r; asm("mov.b64 %0, {%1, %2};" : "=l"(r) : "f"(x), "f"(y)); return r;
}
__device__ __forceinline__ void unpack2(u64 v, float& x, float& y) {
    asm("mov.b64 {%0, %1}, %2;" : "=f"(x), "=f"(y) : "l"(v));
}
__device__ __forceinline__ u64 fma2_(u64 a, u64 b, u64 c) {
    u64 r; asm("fma.rn.f32x2 %0, %1, %2, %3;" : "=l"(r) : "l"(a), "l"(b), "l"(c)); return r;
}
__device__ __forceinline__ u64 add2_(u64 a, u64 b) {
    u64 r; asm("add.rn.f32x2 %0, %1, %2;" : "=l"(r) : "l"(a), "l"(b)); return r;
}

// ---- cp.async ----
__device__ __forceinline__ void cp16(uint32_t dst, const float* src) {
    asm volatile("cp.async.ca.shared.global [%0], [%1], 16;" :: "r"(dst), "l"(src));
}
__device__ __forceinline__ void cp_commit() { asm volatile("cp.async.commit_group;"); }
__device__ __forceinline__ void cp_wait1()  { asm volatile("cp.async.wait_group 1;"); }
__device__ __forceinline__ void cp_wait0()  { asm volatile("cp.async.wait_group 0;"); }

#define SK(b, dd, s, l) ((((b) * DC + (dd)) * 32 + (s)) * 32 + (l))

// =====================================================================
// Transpose: g_kt[n][s][l][d] = k[n][s][d][l].
// Grid (6, 7, 512); each CTA does 4 (32d x 32l) tiles. Coalesced both ways.
// =====================================================================
__global__ __launch_bounds__(256)
void transpose_kernel(const float* __restrict__ k)
{
    __shared__ float tile[32][33];
    const int ns = blockIdx.z;                 // n*T + s
    const int l0 = blockIdx.y * 32;
    const int tid = threadIdx.x;
    const int c  = tid & 31;
    const int r0 = tid >> 5;                   // 0..7
    const size_t base = (size_t)ns * D_ * L_;

    for (int j = 0; j < 4; j++) {
        const int d0 = (blockIdx.x * 4 + j) * 32;
#pragma unroll
        for (int rr = r0; rr < 32; rr += 8)
            tile[rr][c] = (l0 + c < L_) ? k[base + (size_t)(d0 + rr) * L_ + l0 + c] : 0.f;
        __syncthreads();
#pragma unroll
        for (int rr = r0; rr < 32; rr += 8)
            if (l0 + rr < L_)
                g_kt[base + (size_t)(l0 + rr) * D_ + d0 + c] = tile[c][rr];
        __syncthreads();
    }
}

// =====================================================================
// Kernel A (unchanged from R9): partial scores over one d-half.
// Grid (7,16,4): z = tz + 2*dz. Block 128, warp = 4 t's.
// =====================================================================
__global__ __launch_bounds__(128, 3)
void scores_kernel(const float* __restrict__ q, const float* __restrict__ k,
                   const float* __restrict__ peq)
{
    __shared__ float sk[NBUF * DC * 32 * 32];

    const int tid  = threadIdx.x;
    const int lane = tid & 31;
    const int tg   = tid >> 5;
    const int l0   = blockIdx.x * 32;
    const int n    = blockIdx.y;
    const int tz   = blockIdx.z & 1;
    const int dz   = blockIdx.z >> 1;
    const int t0   = tz * 16 + tg * 4;
    const int l    = l0 + lane;
    const bool lv  = (l < L_);
    const int dbase = dz * DH;

    for (int i = tid; i < NBUF * DC * 32 * 32; i += 128) sk[i] = 0.f;
    __syncthreads();

    const uint32_t sbase = (uint32_t)__cvta_generic_to_shared(sk);

    const int ll  = (tid & 7) * 4;
    const bool kv_ok = (l0 + ll < L_);
    const float* kb0 = k + ((size_t)n * T_ * D_ + dbase) * L_ + l0 + ll;

    auto issue = [&](int c, int buf) {
        const size_t cL = (size_t)(c * DC) * L_;
        if (kv_ok) {
#pragma unroll
            for (int i = 0; i < 8; i++) {
                int r  = i * 16 + (tid >> 3);
                int s  = r & 31;
                int dd = r >> 5;
                cp16(sbase + (uint32_t)SK(buf, dd, s, ll) * 4,
                     kb0 + ((size_t)s * D_ + dd) * L_ + cL);
            }
        }
        cp_commit();
    };

    const float* qb0 = q + ((size_t)n * T_ * D_ + dbase) * L_ + l;
    const float* pb0 = peq + (size_t)l * D_ + dbase;

    auto loadq = [&](int c, float (&qr)[4][DC]) {
        if (lv) {
            float4 e = *reinterpret_cast<const float4*>(pb0 + c * DC);
            const size_t cL = (size_t)(c * DC) * L_;
#pragma unroll
            for (int i = 0; i < 4; i++) {
                qr[i][0] = __ldg(qb0 + ((size_t)(t0 + i) * D_ + 0) * L_ + cL) + e.x;
                qr[i][1] = __ldg(qb0 + ((size_t)(t0 + i) * D_ + 1) * L_ + cL) + e.y;
                qr[i][2] = __ldg(qb0 + ((size_t)(t0 + i) * D_ + 2) * L_ + cL) + e.z;
                qr[i][3] = __ldg(qb0 + ((size_t)(t0 + i) * D_ + 3) * L_ + cL) + e.w;
            }
        } else {
#pragma unroll
            for (int i = 0; i < 4; i++)
#pragma unroll
                for (int dd = 0; dd < DC; dd++) qr[i][dd] = 0.f;
        }
    };

    u64 acc[4][16];
#pragma unroll
    for (int i = 0; i < 4; i++)
#pragma unroll
        for (int sp = 0; sp < 16; sp++) acc[i][sp] = 0ULL;

    float qc[4][DC], qn[4][DC];
    issue(0, 0);
    issue(1, 1);
    loadq(0, qc);

    for (int c = 0; c < NCH; ++c) {
        if (c + 1 < NCH) cp_wait1(); else cp_wait0();
        __syncthreads();
        if (c + 2 < NCH) issue(c + 2, (c + 2) % NBUF);
        if (c + 1 < NCH) loadq(c + 1, qn);

        const int buf = c % NBUF;
#pragma unroll
        for (int dd = 0; dd < DC; dd++) {
            u64 qv0 = pack2(qc[0][dd], qc[0][dd]);
            u64 qv1 = pack2(qc[1][dd], qc[1][dd]);
            u64 qv2 = pack2(qc[2][dd], qc[2][dd]);
            u64 qv3 = pack2(qc[3][dd], qc[3][dd]);
            const float* kb = &sk[SK(buf, dd, 0, lane)];
#pragma unroll
            for (int sp = 0; sp < 16; sp++) {
                u64 kv = pack2(kb[(2 * sp) * 32], kb[(2 * sp + 1) * 32]);
                acc[0][sp] = fma2_(qv0, kv, acc[0][sp]);
                acc[1][sp] = fma2_(qv1, kv, acc[1][sp]);
                acc[2][sp] = fma2_(qv2, kv, acc[2][sp]);
                acc[3][sp] = fma2_(qv3, kv, acc[3][sp]);
            }
        }
#pragma unroll
        for (int i = 0; i < 4; i++)
#pragma unroll
            for (int dd = 0; dd < DC; dd++) qc[i][dd] = qn[i][dd];
    }

    if (lv) {
#pragma unroll
        for (int i = 0; i < 4; i++) {
            float* ap = &g_part[dz][(((size_t)n * T_ + t0 + i) * T_) * L_ + l];
#pragma unroll
            for (int sp = 0; sp < 16; sp++) {
                float x, y;
                unpack2(acc[i][sp], x, y);
                ap[(2 * sp) * L_]     = x;
                ap[(2 * sp + 1) * L_] = y;
            }
        }
    }
}

// =====================================================================
// Reduce + softmax: g_a2[n][s][t][l] = dup(softmax_s(sum_dz g_part)).
// One thread per (n,t,l); reads and writes fully coalesced along l.
// =====================================================================
__global__ __launch_bounds__(256)
void reduce_softmax_kernel()
{
    const int idx = blockIdx.x * 256 + threadIdx.x;
    if (idx >= N_ * T_ * L_) return;
    const int l = idx % L_;
    const int t = (idx / L_) % T_;
    const int n = idx / (T_ * L_);

    const size_t base = (((size_t)n * T_ + t) * T_) * L_ + l;
    const float scale = 0.03608439182435161f;  // 1/sqrt(768)

    float v[32];
    float m = -1e30f;
#pragma unroll
    for (int s = 0; s < 32; s++) {
        v[s] = (g_part[0][base + s * L_] + g_part[1][base + s * L_]) * scale;
        m = fmaxf(m, v[s]);
    }
    float sum = 0.f;
#pragma unroll
    for (int s = 0; s < 32; s++) { float e = __expf(v[s] - m); v[s] = e; sum += e; }
    const float inv = 1.f / sum;
#pragma unroll
    for (int s = 0; s < 32; s++) {
        float a = v[s] * inv;
        g_a2[((size_t)n * 1024 + s * 32 + t) * L_ + l] = pack2(a, a);
    }
}

// =====================================================================
// Kernel B v2: out[n,t,l,d] = sum_s a[t,s,l] * kt[n,s,l,d] + pek[l,d].
// Grid (49, 16, 2): (l-block of 4, n, d-half). Block 128 = 4 warps,
// warp w owns l = l0+w; lanes = d-pairs (u64). a tile in smem, read by
// broadcast LDS.128; kt read coalesced LDG.64. NO barriers in mainloop.
// =====================================================================
__global__ __launch_bounds__(128, 4)
void out_kernel(const float* __restrict__ pek, float* __restrict__ out)
{
    __shared__ u64 sa[4 * 1024];   // [l-idx][s*32+t]  32 KB

    const int tid  = threadIdx.x;
    const int lane = tid & 31;
    const int w    = tid >> 5;               // warp = l index within block
    const int l0   = blockIdx.x * 4;         // 196 = 49*4, always full
    const int n    = blockIdx.y;
    const int dz   = blockIdx.z;

    // ---- prologue: load a tile for 4 l's (all 32s x 32t), coalesced-ish
#pragma unroll
    for (int i = 0; i < 32; i++) {
        int flat = i * 128 + tid;             // 0..4095
        int st = flat >> 2;                   // s*32+t
        int li = flat & 3;
        sa[li * 1024 + st] = g_a2[((size_t)n * 1024 + st) * L_ + l0 + li];
    }
    __syncthreads();

    const int l = l0 + w;
    const u64* sa_w = sa + w * 1024;
    const float* ktb = g_kt + (((size_t)n * T_) * L_ + l) * D_;
    const int SSTRIDE = L_ * D_ / 2;          // u64 stride between s

    for (int dc = 0; dc < 6; dc++) {
        const int d0 = dz * DH + dc * 64 + 2 * lane;
        const u64* kp = reinterpret_cast<const u64*>(ktb + d0);

        u64 oc[32];
#pragma unroll
        for (int t = 0; t < 32; t++) oc[t] = 0ULL;

        u64 kvc = __ldg(kp);
#pragma unroll 4
        for (int s = 0; s < 32; s++) {
            u64 kvn = 0ULL;
            if (s < 31) kvn = __ldg(kp + (s + 1) * SSTRIDE);
            const ulonglong2* ap = reinterpret_cast<const ulonglong2*>(sa_w + s * 32);
#pragma unroll
            for (int tp = 0; tp < 16; tp++) {
                ulonglong2 a = ap[tp];
                oc[2 * tp]     = fma2_(a.x, kvc, oc[2 * tp]);
                oc[2 * tp + 1] = fma2_(a.y, kvc, oc[2 * tp + 1]);
            }
            kvc = kvn;
        }

        // epilogue: add pek, store coalesced along d
        const u64 pe = *reinterpret_cast<const u64*>(pek + (size_t)l * D_ + d0);
#pragma unroll
        for (int t = 0; t < 32; t++) {
            *reinterpret_cast<u64*>(
                out + (((size_t)n * T_ + t) * L_ + l) * D_ + d0) = add2_(oc[t], pe);
        }
    }
}

extern "C" void kernel_launch(void* const* d_in, const int* in_sizes, int n_in,
                              void* d_out, int out_size)
{
    const float* q   = (const float*)d_in[0];
    const float* k   = (const float*)d_in[1];
    const float* peq = (const float*)d_in[2];
    const float* pek = (const float*)d_in[3];
    float* out = (float*)d_out;

    transpose_kernel<<<dim3(6, 7, N_ * T_), 256>>>(k);
    scores_kernel<<<dim3(NLB, N_, 4), 128>>>(q, k, peq);
    reduce_softmax_kernel<<<(N_ * T_ * L_ + 255) / 256, 256>>>();
    out_kernel<<<dim3(49, N_, 2), 128>>>(pek, out);
}